// round 17
// baseline (speedup 1.0000x reference)
#include <cuda_runtime.h>
#include <cuda_fp16.h>
#include <cstdint>

#define BB   2
#define SEQ  2048
#define DIN  1024
#define DOUT 1024
#define NH   16
#define HD   64
#define MROWS (BB*SEQ)   // 4096
#define NTILE 16
#define NTI   (BB*NH*NTILE)   // 512

// Scratch (allocation-free -> __device__ globals)
__device__ __half g_q[BB*NH*SEQ*HD];   // q pre-scaled by 0.125*log2e
__device__ __half g_k[BB*NH*SEQ*HD];
__device__ __half g_v[BB*NH*SEQ*HD];
__device__ __half g_ctx[MROWS*DOUT];
__device__ __half g_wh[4*DIN*DOUT];    // fp16 weights, natural [K,N] (q,k,v,o)
__device__ __half g_xh[MROWS*DIN];
__device__ __half g_po[2][NTI*128*64]; // unnormalized O per part (scaled 1/16)
__device__ float  g_pl[2][NTI*128];    // sum of exp2(s) per row (scaled 1/16)

#define QSCALE 0.1803368801111713f     // 0.125 * log2(e)
#define PSCALE 0.0625f                 // partial scaling (power of 2; cancels in merge)

__constant__ int TL_OF[32] = {15,15,14,14,13,13,12,12,11,11,10,10, 9, 9, 8, 8,
                               7, 7, 6, 6, 5, 5, 4, 4, 3, 3, 2, 2, 1, 1, 0, 0};
__constant__ int PT_OF[32] = { 1, 0, 0, 1, 1, 0, 0, 1, 1, 0, 0, 1, 1, 0, 0, 1,
                               1, 0, 0, 1, 1, 0, 0, 1, 1, 0, 0, 1, 1, 0, 0, 1};

// ---------------------------------------------------------------------------
// helpers
// ---------------------------------------------------------------------------
__device__ __forceinline__ uint32_t h2u(float a, float b) {
    __half2 h = __floats2half2_rn(a, b);
    return *(uint32_t*)&h;
}

__device__ __forceinline__ uint32_t smem_u32(const void* p) {
    uint32_t a;
    asm("{ .reg .u64 t; cvta.to.shared.u64 t, %1; cvt.u32.u64 %0, t; }"
        : "=r"(a) : "l"(p));
    return a;
}

#define CP16(dst, src) \
    asm volatile("cp.async.cg.shared.global [%0], [%1], 16;" \
                 :: "r"(dst), "l"(src) : "memory")
#define CP_COMMIT() asm volatile("cp.async.commit_group;" ::: "memory")
#define CP_WAIT0()  asm volatile("cp.async.wait_group 0;" ::: "memory")
#define CP_WAIT1()  asm volatile("cp.async.wait_group 1;" ::: "memory")
#define CP_WAIT2()  asm volatile("cp.async.wait_group 2;" ::: "memory")

__device__ __forceinline__ void mma_f16(
    float& c0, float& c1, float& c2, float& c3,
    uint32_t a0, uint32_t a1, uint32_t a2, uint32_t a3,
    uint32_t b0, uint32_t b1)
{
    asm volatile(
        "mma.sync.aligned.m16n8k16.row.col.f32.f16.f16.f32 "
        "{%0,%1,%2,%3}, {%4,%5,%6,%7}, {%8,%9}, {%0,%1,%2,%3};\n"
        : "+f"(c0), "+f"(c1), "+f"(c2), "+f"(c3)
        : "r"(a0), "r"(a1), "r"(a2), "r"(a3), "r"(b0), "r"(b1));
}

__device__ __forceinline__ void ldsm4(
    uint32_t& r0, uint32_t& r1, uint32_t& r2, uint32_t& r3, uint32_t addr)
{
    asm volatile("ldmatrix.sync.aligned.m8n8.x4.shared.b16 {%0,%1,%2,%3}, [%4];"
                 : "=r"(r0), "=r"(r1), "=r"(r2), "=r"(r3) : "r"(addr));
}

__device__ __forceinline__ void ldsm4t(
    uint32_t& r0, uint32_t& r1, uint32_t& r2, uint32_t& r3, uint32_t addr)
{
    asm volatile("ldmatrix.sync.aligned.m8n8.x4.trans.shared.b16 {%0,%1,%2,%3}, [%4];"
                 : "=r"(r0), "=r"(r1), "=r"(r2), "=r"(r3) : "r"(addr));
}

// ---------------------------------------------------------------------------
// Combined conversion kernel: blocks [0,2048) -> x, [2048, 4096) -> weights
// ---------------------------------------------------------------------------
__global__ __launch_bounds__(256) void cvt_all(
    const float* __restrict__ x,
    const float* __restrict__ Wq, const float* __restrict__ Wk,
    const float* __restrict__ Wv, const float* __restrict__ Wo)
{
    const float* src;
    __half* dst;
    size_t i;
    if (blockIdx.x < 2048) {
        src = x; dst = g_xh;
        i = ((size_t)blockIdx.x * 256 + threadIdx.x) * 8;
    } else {
        int b = blockIdx.x - 2048;
        int z = b >> 9;                 // 512 blocks per weight
        src = (z == 0) ? Wq : (z == 1) ? Wk : (z == 2) ? Wv : Wo;
        dst = g_wh + ((size_t)z << 20);
        i = ((size_t)(b & 511) * 256 + threadIdx.x) * 8;
    }
    float4 a = *(const float4*)(src + i);
    float4 b4 = *(const float4*)(src + i + 4);
    uint4 o;
    o.x = h2u(a.x, a.y); o.y = h2u(a.z, a.w);
    o.z = h2u(b4.x, b4.y); o.w = h2u(b4.z, b4.w);
    *(uint4*)(dst + i) = o;
}

// ---------------------------------------------------------------------------
// fp16 HMMA GEMM, tile 128x128x32, 256 thr (8 warps 2m x 4n), warp tile 64x32,
// 4-stage cp.async ring, 2 CTAs/SM. A ldmatrix, B ldmatrix.trans from [K,N].
// ---------------------------------------------------------------------------
#define ASTRH 40
#define BSTRH 136
#define A_BYTES (128 * ASTRH * 2)      // 10240
#define B_BYTES (32 * BSTRH * 2)       // 8704
#define STAGE_B (A_BYTES + B_BYTES)    // 18944
#define GEMM_SMEM (4 * STAGE_B)        // 75776

struct GemmAcc { float c[4][4][4]; };

__device__ __forceinline__ void gemm_cp_body(
    const __half* __restrict__ Ag,
    const __half* __restrict__ Bg,
    GemmAcc& acc, char* sm)
{
    const int t    = threadIdx.x;
    const int wid  = t >> 5, lane = t & 31;
    const int wm   = (wid & 1) * 64;
    const int wn   = (wid >> 1) * 32;
    const uint32_t sb0 = smem_u32(sm);

    uint32_t aAddr[4], bAddr[2];
    #pragma unroll
    for (int mf = 0; mf < 4; mf++)
        aAddr[mf] = ((wm + mf * 16 + (lane & 15)) * ASTRH
                     + ((lane & 16) ? 8 : 0)) * 2;
    #pragma unroll
    for (int nfp = 0; nfp < 2; nfp++)
        bAddr[nfp] = A_BYTES + ((lane & 15) * BSTRH
                     + wn + nfp * 16 + ((lane & 16) ? 8 : 0)) * 2;

    #pragma unroll
    for (int mf = 0; mf < 4; mf++)
        #pragma unroll
        for (int nf = 0; nf < 4; nf++)
            #pragma unroll
            for (int r = 0; r < 4; r++) acc.c[mf][nf][r] = 0.f;

    uint32_t adst[2], bdst[2];
    const __half* asrc[2];
    const __half* bsrc[2];
    #pragma unroll
    for (int i = 0; i < 2; i++) {
        int c = t + i * 256;
        int ar = c >> 2, ak = c & 3;
        adst[i] = ar * (ASTRH * 2) + ak * 16;
        asrc[i] = Ag + (size_t)ar * 1024 + ak * 8;
        int br = c >> 4, bn = c & 15;
        bdst[i] = A_BYTES + br * (BSTRH * 2) + bn * 16;
        bsrc[i] = Bg + (size_t)br * 1024 + bn * 8;
    }

    #pragma unroll
    for (int st = 0; st < 3; st++) {
        const uint32_t sn = sb0 + st * STAGE_B;
        #pragma unroll
        for (int i = 0; i < 2; i++) {
            CP16(sn + adst[i], asrc[i] + st * 32);
            CP16(sn + bdst[i], bsrc[i] + (size_t)st * 32 * 1024);
        }
        CP_COMMIT();
    }

    for (int kt = 0; kt < 32; kt++) {
        if (kt < 30) CP_WAIT2();
        else if (kt == 30) CP_WAIT1();
        else CP_WAIT0();
        __syncthreads();
        if (kt + 3 < 32) {
            const uint32_t sn = sb0 + ((kt + 3) & 3) * STAGE_B;
            #pragma unroll
            for (int i = 0; i < 2; i++) {
                CP16(sn + adst[i], asrc[i] + (kt + 3) * 32);
                CP16(sn + bdst[i], bsrc[i] + (size_t)(kt + 3) * 32 * 1024);
            }
            CP_COMMIT();
        }

        const uint32_t su = sb0 + (kt & 3) * STAGE_B;

        #pragma unroll
        for (int ks = 0; ks < 2; ks++) {
            uint32_t b[4][2];
            #pragma unroll
            for (int nfp = 0; nfp < 2; nfp++)
                ldsm4t(b[2*nfp][0], b[2*nfp][1], b[2*nfp+1][0], b[2*nfp+1][1],
                       su + bAddr[nfp] + ks * 16 * (BSTRH * 2));
            #pragma unroll
            for (int mf = 0; mf < 4; mf++) {
                uint32_t a0, a1, a2, a3;
                ldsm4(a0, a1, a2, a3, su + aAddr[mf] + ks * 32);
                #pragma unroll
                for (int nf = 0; nf < 4; nf++)
                    mma_f16(acc.c[mf][nf][0], acc.c[mf][nf][1],
                            acc.c[mf][nf][2], acc.c[mf][nf][3],
                            a0, a1, a2, a3, b[nf][0], b[nf][1]);
            }
        }
    }
}

__global__ __launch_bounds__(256, 2) void qkv_gemm()
{
    extern __shared__ char sm[];
    const int m0 = blockIdx.y * 128, n0 = blockIdx.x * 128;
    GemmAcc acc;
    gemm_cp_body(g_xh + (size_t)m0 * DIN,
                 g_wh + ((size_t)blockIdx.z << 20) + n0, acc, sm);

    __half* dst = (blockIdx.z == 0) ? g_q : (blockIdx.z == 1) ? g_k : g_v;
    const float qs = (blockIdx.z == 0) ? QSCALE : 1.0f;
    const int t = threadIdx.x, wid = t >> 5, lane = t & 31;
    const int lr = lane >> 2, lc = lane & 3;
    const int wm = (wid & 1) * 64, wn = (wid >> 1) * 32;

    #pragma unroll
    for (int mf = 0; mf < 4; mf++) {
        #pragma unroll
        for (int nf = 0; nf < 4; nf++) {
            int cb = n0 + wn + nf * 8 + 2 * lc;
            int h = cb >> 6, d = cb & 63;
            #pragma unroll
            for (int half = 0; half < 2; half++) {
                int m = m0 + wm + mf * 16 + lr + half * 8;
                int b = m >> 11, n = m & 2047;
                *(uint32_t*)&dst[((size_t)(b * 16 + h) * SEQ + n) * HD + d] =
                    h2u(acc.c[mf][nf][half*2] * qs, acc.c[mf][nf][half*2+1] * qs);
            }
        }
    }
}

__global__ __launch_bounds__(256, 2) void proj_gemm(
    const float* __restrict__ bo, float* __restrict__ out)
{
    extern __shared__ char sm[];
    const int m0 = blockIdx.y * 128, n0 = blockIdx.x * 128;
    GemmAcc acc;
    gemm_cp_body(g_ctx + (size_t)m0 * DOUT,
                 g_wh + ((size_t)3 << 20) + n0, acc, sm);

    const int t = threadIdx.x, wid = t >> 5, lane = t & 31;
    const int lr = lane >> 2, lc = lane & 3;
    const int wm = (wid & 1) * 64, wn = (wid >> 1) * 32;

    #pragma unroll
    for (int mf = 0; mf < 4; mf++) {
        #pragma unroll
        for (int nf = 0; nf < 4; nf++) {
            int cb = n0 + wn + nf * 8 + 2 * lc;
            float2 bias = *(const float2*)&bo[cb];
            #pragma unroll
            for (int half = 0; half < 2; half++) {
                int m = m0 + wm + mf * 16 + lr + half * 8;
                *(float2*)&out[(size_t)m * DOUT + cb] =
                    make_float2(acc.c[mf][nf][half*2] + bias.x,
                                acc.c[mf][nf][half*2+1] + bias.y);
            }
        }
    }
}

// ---------------------------------------------------------------------------
// Split-KV fp16 flash attention, m32 warp tiles, DOUBLE-buffered K+V with a
// single commit group per chunk -> ONE wait + ONE syncthreads per chunk.
// Buffer-safety: prefetch of chunk ch+1 (into buffer (ch+1)&1) is issued only
// after the top sync of ch, which proves buffer (ch+1)&1's previous contents
// (chunk ch-1) are fully consumed by all threads.
// ---------------------------------------------------------------------------
#define KSTRH 72
#define VSTRH 72
#define QSTRH 72
#define K_BYTES_T (64*KSTRH*2)   // 9216
#define V_BYTES_T (64*VSTRH*2)   // 9216
#define Q_BYTES_T (128*QSTRH*2)  // 18432
#define ATTN_SMEM (2*K_BYTES_T + 2*V_BYTES_T + Q_BYTES_T)   // 55296

__global__ __launch_bounds__(128, 2) void attn_kernel()
{
    extern __shared__ char smc[];
    const uint32_t ksm = smem_u32(smc);              // 2 x K buffers
    const uint32_t vsm = ksm + 2 * K_BYTES_T;        // 2 x V buffers
    const uint32_t qsm = vsm + 2 * V_BYTES_T;

    const int t    = threadIdx.x;
    const int wid  = t >> 5, lane = t & 31;
    const int lr   = lane >> 2, lc = lane & 3;

    const int u    = blockIdx.x;
    const int lvl  = u >> 5, bh = u & 31;
    const int tl   = TL_OF[lvl];
    const int part = PT_OF[lvl];
    const int Ah   = tl + 1;
    const int c0   = part ? Ah : 0;
    const int c1   = part ? (2 * tl + 2) : Ah;
    const int q0   = tl * 128;
    const int ti   = bh * NTILE + tl;

    const __half* qbase = g_q + (size_t)(bh * SEQ + q0) * HD;
    const __half* kbase = g_k + (size_t)bh * SEQ * HD;
    const __half* vbase = g_v + (size_t)bh * SEQ * HD;

    // fragment base addresses (buffer 0); add (ch&1)*bytes at use
    uint32_t kAddr[4], vAddr[4], qAddr[2];
    #pragma unroll
    for (int nfp = 0; nfp < 4; nfp++) {
        kAddr[nfp] = ksm + ((nfp * 16 + (lane & 7) + ((lane & 16) ? 8 : 0)) * KSTRH
                     + ((lane & 8) ? 8 : 0)) * 2;
        vAddr[nfp] = vsm + ((lane & 15) * VSTRH
                     + nfp * 16 + ((lane & 16) ? 8 : 0)) * 2;
    }
    #pragma unroll
    for (int mf = 0; mf < 2; mf++)
        qAddr[mf] = qsm + (((32 * wid + mf * 16 + (lane & 15)) * QSTRH)
                     + ((lane & 16) ? 8 : 0)) * 2;

    // copy maps (per-thread)
    int cpr[4], cps[4];
    #pragma unroll
    for (int i = 0; i < 4; i++) {
        int c = t + i * 128;
        cpr[i] = c >> 3; cps[i] = c & 7;
    }

    // stage Q (group 0)
    #pragma unroll
    for (int i = 0; i < 8; i++) {
        int c = t + i * 128;
        int r = c >> 3, sb = c & 7;
        CP16(qsm + r * (QSTRH*2) + sb * 16, qbase + (size_t)r * HD + sb * 8);
    }
    CP_COMMIT();
    // K+V chunk c0 (group 1, buffer c0&1)
    {
        const __half* kp = kbase + (size_t)c0 * 64 * HD;
        const __half* vp = vbase + (size_t)c0 * 64 * HD;
        const uint32_t kb2 = ksm + (c0 & 1) * K_BYTES_T;
        const uint32_t vb2 = vsm + (c0 & 1) * V_BYTES_T;
        #pragma unroll
        for (int i = 0; i < 4; i++) {
            CP16(kb2 + cpr[i] * (KSTRH*2) + cps[i] * 16,
                 kp + (size_t)cpr[i] * HD + cps[i] * 8);
            CP16(vb2 + cpr[i] * (VSTRH*2) + cps[i] * 16,
                 vp + (size_t)cpr[i] * HD + cps[i] * 8);
        }
        CP_COMMIT();
    }

    CP_WAIT1();          // Q staged (K/V group may still fly)
    __syncthreads();

    uint32_t qa[4][8];
    #pragma unroll
    for (int ks = 0; ks < 4; ks++) {
        ldsm4(qa[ks][0], qa[ks][1], qa[ks][2], qa[ks][3], qAddr[0] + ks * 32);
        ldsm4(qa[ks][4], qa[ks][5], qa[ks][6], qa[ks][7], qAddr[1] + ks * 32);
    }

    float lsum[4];
    #pragma unroll
    for (int i = 0; i < 4; i++) lsum[i] = 0.f;
    float o[2][8][4];
    #pragma unroll
    for (int mf = 0; mf < 2; mf++)
        #pragma unroll
        for (int nf = 0; nf < 8; nf++)
            #pragma unroll
            for (int r = 0; r < 4; r++) o[mf][nf][r] = 0.f;

    for (int ch = c0; ch < c1; ch++) {
        const int kb = ch * 64;
        const uint32_t kofs = (ch & 1) * K_BYTES_T;
        const uint32_t vofs = (ch & 1) * V_BYTES_T;

        CP_WAIT0();          // K+V[ch] arrived (single group)
        __syncthreads();     // visible to all; prev chunk fully consumed

        if (ch + 1 < c1) {   // prefetch next chunk into the other buffer
            const __half* kp = kbase + (size_t)(kb + 64) * HD;
            const __half* vp = vbase + (size_t)(kb + 64) * HD;
            const uint32_t kb2 = ksm + ((ch + 1) & 1) * K_BYTES_T;
            const uint32_t vb2 = vsm + ((ch + 1) & 1) * V_BYTES_T;
            #pragma unroll
            for (int i = 0; i < 4; i++) {
                CP16(kb2 + cpr[i] * (KSTRH*2) + cps[i] * 16,
                     kp + (size_t)cpr[i] * HD + cps[i] * 8);
                CP16(vb2 + cpr[i] * (VSTRH*2) + cps[i] * 16,
                     vp + (size_t)cpr[i] * HD + cps[i] * 8);
            }
            CP_COMMIT();
        }

        // ---- S = Q K^T ----
        float s[2][8][4];
        #pragma unroll
        for (int mf = 0; mf < 2; mf++)
            #pragma unroll
            for (int nf = 0; nf < 8; nf++)
                #pragma unroll
                for (int r = 0; r < 4; r++) s[mf][nf][r] = 0.f;

        #pragma unroll
        for (int ks = 0; ks < 4; ks++) {
            #pragma unroll
            for (int nfp = 0; nfp < 4; nfp++) {
                uint32_t b0, b1, b2, b3;
                ldsm4(b0, b1, b2, b3, kAddr[nfp] + kofs + ks * 32);
                const int nf = 2 * nfp;
                mma_f16(s[0][nf][0], s[0][nf][1], s[0][nf][2], s[0][nf][3],
                        qa[ks][0], qa[ks][1], qa[ks][2], qa[ks][3], b0, b1);
                mma_f16(s[1][nf][0], s[1][nf][1], s[1][nf][2], s[1][nf][3],
                        qa[ks][4], qa[ks][5], qa[ks][6], qa[ks][7], b0, b1);
                mma_f16(s[0][nf+1][0], s[0][nf+1][1], s[0][nf+1][2], s[0][nf+1][3],
                        qa[ks][0], qa[ks][1], qa[ks][2], qa[ks][3], b2, b3);
                mma_f16(s[1][nf+1][0], s[1][nf+1][1], s[1][nf+1][2], s[1][nf+1][3],
                        qa[ks][4], qa[ks][5], qa[ks][6], qa[ks][7], b2, b3);
            }
        }

        // ---- causal mask (diagonal chunks only) ----
        if (kb >= q0) {
            const int rb = q0 + 32 * wid + lr;
            #pragma unroll
            for (int mf = 0; mf < 2; mf++) {
                int r0 = rb + mf * 16, r1 = r0 + 8;
                #pragma unroll
                for (int nf = 0; nf < 8; nf++) {
                    int cc0 = kb + nf * 8 + 2 * lc, cc1 = cc0 + 1;
                    if (cc0 > r0) s[mf][nf][0] = -1e30f;
                    if (cc1 > r0) s[mf][nf][1] = -1e30f;
                    if (cc0 > r1) s[mf][nf][2] = -1e30f;
                    if (cc1 > r1) s[mf][nf][3] = -1e30f;
                }
            }
        }

        // ---- p = exp2(s), packed straight into PV A-fragments ----
        uint32_t pa[2][4][4];
        #pragma unroll
        for (int mf = 0; mf < 2; mf++) {
            #pragma unroll
            for (int nf = 0; nf < 8; nf++) {
                float p0 = exp2f(s[mf][nf][0]);
                float p1 = exp2f(s[mf][nf][1]);
                float p2 = exp2f(s[mf][nf][2]);
                float p3 = exp2f(s[mf][nf][3]);
                lsum[2*mf]   += p0 + p1;
                lsum[2*mf+1] += p2 + p3;
                pa[mf][nf >> 1][(nf & 1) * 2 + 0] = h2u(p0, p1);
                pa[mf][nf >> 1][(nf & 1) * 2 + 1] = h2u(p2, p3);
            }
        }

        // ---- O += P @ V ----
        #pragma unroll
        for (int ks = 0; ks < 4; ks++) {
            #pragma unroll
            for (int nfp = 0; nfp < 4; nfp++) {
                uint32_t b0, b1, b2, b3;
                ldsm4t(b0, b1, b2, b3, vAddr[nfp] + vofs + ks * 16 * (VSTRH * 2));
                const int nf = 2 * nfp;
                mma_f16(o[0][nf][0], o[0][nf][1], o[0][nf][2], o[0][nf][3],
                        pa[0][ks][0], pa[0][ks][1], pa[0][ks][2], pa[0][ks][3], b0, b1);
                mma_f16(o[1][nf][0], o[1][nf][1], o[1][nf][2], o[1][nf][3],
                        pa[1][ks][0], pa[1][ks][1], pa[1][ks][2], pa[1][ks][3], b0, b1);
                mma_f16(o[0][nf+1][0], o[0][nf+1][1], o[0][nf+1][2], o[0][nf+1][3],
                        pa[0][ks][0], pa[0][ks][1], pa[0][ks][2], pa[0][ks][3], b2, b3);
                mma_f16(o[1][nf+1][0], o[1][nf+1][1], o[1][nf+1][2], o[1][nf+1][3],
                        pa[1][ks][0], pa[1][ks][1], pa[1][ks][2], pa[1][ks][3], b2, b3);
            }
        }
        // no bottom barrier: next chunk's top sync proves this buffer is free
    }

    #pragma unroll
    for (int off = 1; off < 4; off <<= 1)
        #pragma unroll
        for (int i = 0; i < 4; i++)
            lsum[i] += __shfl_xor_sync(0xffffffffu, lsum[i], off);

    // write partials as fp16 (scaled by 1/16; l scaled identically -> cancels)
    __half* po = g_po[part];
    const int rb = 32 * wid + lr;
    #pragma unroll
    for (int mf = 0; mf < 2; mf++) {
        int r0 = rb + mf * 16, r1 = r0 + 8;
        #pragma unroll
        for (int nf = 0; nf < 8; nf++) {
            int cb = nf * 8 + 2 * lc;
            *(uint32_t*)&po[((size_t)ti * 128 + r0) * 64 + cb] =
                h2u(o[mf][nf][0] * PSCALE, o[mf][nf][1] * PSCALE);
            *(uint32_t*)&po[((size_t)ti * 128 + r1) * 64 + cb] =
                h2u(o[mf][nf][2] * PSCALE, o[mf][nf][3] * PSCALE);
        }
        if (lc == 0) {
            g_pl[part][ti * 128 + r0] = lsum[2*mf]   * PSCALE;
            g_pl[part][ti * 128 + r1] = lsum[2*mf+1] * PSCALE;
        }
    }
}

// ---------------------------------------------------------------------------
// Merge partials -> g_ctx fp16: O = (oA + oB) / (lA + lB). grid 512, block 256.
// ---------------------------------------------------------------------------
__global__ __launch_bounds__(256) void merge_attn()
{
    const int ti = blockIdx.x, t = threadIdx.x;
    const int r = t >> 1, hh = t & 1;
    const int bh = ti >> 4, tl = ti & 15;
    const int b = bh >> 4, h = bh & 15;
    const int grow = tl * 128 + r;

    const int ri = ti * 128 + r;
    float inv = 1.f / (g_pl[0][ri] + g_pl[1][ri]);

    const __half2* pa = (const __half2*)&g_po[0][((size_t)ri) * 64 + hh * 32];
    const __half2* pb = (const __half2*)&g_po[1][((size_t)ri) * 64 + hh * 32];
    __half2* dst = (__half2*)&g_ctx[(size_t)(b * SEQ + grow) * DOUT + h * HD + hh * 32];

    #pragma unroll
    for (int i = 0; i < 16; i++) {
        float2 va = __half22float2(pa[i]);
        float2 vb = __half22float2(pb[i]);
        dst[i] = __floats2half2_rn((va.x + vb.x) * inv, (va.y + vb.y) * inv);
    }
}

// ---------------------------------------------------------------------------
extern "C" void kernel_launch(void* const* d_in, const int* in_sizes, int n_in,
                              void* d_out, int out_size)
{
    const float* x  = (const float*)d_in[0];
    const float* Wq = (const float*)d_in[1];
    const float* Wk = (const float*)d_in[2];
    const float* Wv = (const float*)d_in[3];
    const float* Wo = (const float*)d_in[4];
    const float* bo = (const float*)d_in[5];
    float* out = (float*)d_out;

    cudaFuncSetAttribute(attn_kernel,
                         cudaFuncAttributeMaxDynamicSharedMemorySize, ATTN_SMEM);
    cudaFuncSetAttribute(qkv_gemm,
                         cudaFuncAttributeMaxDynamicSharedMemorySize, GEMM_SMEM);
    cudaFuncSetAttribute(proj_gemm,
                         cudaFuncAttributeMaxDynamicSharedMemorySize, GEMM_SMEM);

    cvt_all<<<4096, 256>>>(x, Wq, Wk, Wv, Wo);
    qkv_gemm<<<dim3(DOUT / 128, MROWS / 128, 3), 256, GEMM_SMEM>>>();
    attn_kernel<<<1024, 128, ATTN_SMEM>>>();
    merge_attn<<<NTI, 256>>>();
    proj_gemm<<<dim3(DOUT / 128, MROWS / 128), 256, GEMM_SMEM>>>(bo, out);
}